// round 7
// baseline (speedup 1.0000x reference)
#include <cuda_runtime.h>
#include <cuda_bf16.h>
#include <cstdint>

#define BATCH 8
#define SEQ   2048
#define DIM   512
#define NQKV  1536   // 3*DIM

// ---------------------------------------------------------------------------
// Scratch (device globals)
// ---------------------------------------------------------------------------
__device__ __align__(16) float g_QKV[(long)BATCH * SEQ * NQKV];  // 96 MB
__device__ __align__(16) float g_Vt [(long)BATCH * DIM * SEQ];   // 32 MB
__device__ __align__(16) float g_S  [(long)BATCH * SEQ * SEQ];   // 128 MB
__device__ __align__(16) float g_WT [(long)NQKV * DIM];          // 3 MB

// ---------------------------------------------------------------------------
// PTX helpers (baseline ISA: ldmatrix + mma.sync, sm_80+)
// ---------------------------------------------------------------------------
__device__ __forceinline__ uint32_t smem_u32(const void* p) {
    uint32_t a;
    asm("{ .reg .u64 t; cvta.to.shared.u64 t, %1; cvt.u32.u64 %0, t; }"
        : "=r"(a) : "l"(p));
    return a;
}
__device__ __forceinline__ void ldsm_x4(uint32_t addr, uint32_t* r) {
    asm volatile("ldmatrix.sync.aligned.m8n8.x4.shared.b16 {%0,%1,%2,%3}, [%4];"
                 : "=r"(r[0]), "=r"(r[1]), "=r"(r[2]), "=r"(r[3]) : "r"(addr));
}
__device__ __forceinline__ void mma_bf16(float* c, const uint32_t* a, const uint32_t* b) {
    asm volatile(
        "mma.sync.aligned.m16n8k16.row.col.f32.bf16.bf16.f32 "
        "{%0,%1,%2,%3}, {%4,%5,%6,%7}, {%8,%9}, {%0,%1,%2,%3};"
        : "+f"(c[0]), "+f"(c[1]), "+f"(c[2]), "+f"(c[3])
        : "r"(a[0]), "r"(a[1]), "r"(a[2]), "r"(a[3]), "r"(b[0]), "r"(b[1]));
}

// Convert float4 -> hi/lo bf16 pairs and store 8B each to smem
__device__ __forceinline__ void cvt_store(char* hi, char* lo, uint32_t off, float4 v) {
    __nv_bfloat162 h01 = __floats2bfloat162_rn(v.x, v.y);
    __nv_bfloat162 h23 = __floats2bfloat162_rn(v.z, v.w);
    __nv_bfloat162 l01 = __floats2bfloat162_rn(v.x - __bfloat162float(h01.x),
                                               v.y - __bfloat162float(h01.y));
    __nv_bfloat162 l23 = __floats2bfloat162_rn(v.z - __bfloat162float(h23.x),
                                               v.w - __bfloat162float(h23.y));
    *reinterpret_cast<uint2*>(hi + off) =
        make_uint2(*reinterpret_cast<uint32_t*>(&h01), *reinterpret_cast<uint32_t*>(&h23));
    *reinterpret_cast<uint2*>(lo + off) =
        make_uint2(*reinterpret_cast<uint32_t*>(&l01), *reinterpret_cast<uint32_t*>(&l23));
}

// ---------------------------------------------------------------------------
// Tensor-core GEMM: C[M,N] = alpha * A[M,K] @ B[N,K]^T  (fp32 in/out)
// In-kernel split precision (hi+lo bf16, 3 MMA terms), CTA tile 128x128,
// k-chunk 32, double-buffered smem, 1 sync per chunk.
// 512 threads / 16 warps (4x4 grid of 32x32 warp tiles) for issue overlap.
// ---------------------------------------------------------------------------
#define ROWB   80                  // padded smem row bytes (40 bf16): conflict-free ldsm
#define TILEB  (128 * ROWB)        // 10240
#define STAGEB (4 * TILEB)         // Ahi, Alo, Bhi, Blo
#define SMEMB  (2 * STAGEB)        // 81920

__global__ __launch_bounds__(512, 1)
void tc_gemm4(const float* __restrict__ A, const float* __restrict__ B,
              float* __restrict__ C, int M, int N, int K,
              int ldA, int ldB, int ldC, long sA, long sB, long sC, float alpha)
{
    extern __shared__ __align__(16) char smem[];

    const long zb = blockIdx.z;
    A += zb * sA;
    B += zb * sB;
    C += zb * sC;

    const int tid  = threadIdx.x;
    const int wid  = tid >> 5;
    const int lane = tid & 31;
    const int wm   = wid & 3;   // 4 warps along M (32 rows each)
    const int wn   = wid >> 2;  // 4 warps along N (32 cols each)

    const int rowA = blockIdx.y * 128;
    const int rowB = blockIdx.x * 128;

    // Loader mapping: 1024 float4 per operand tile; 2 per thread
    const int lr0 = tid >> 3;              // rows 0..63
    const int lr1 = (tid + 512) >> 3;      // rows 64..127
    const int lc4 = tid & 7;

    // ldmatrix lane selectors
    const int aRow = lane & 15;
    const int aK   = (lane >> 4) * 8;
    const int bRow = (lane & 7) + ((lane >> 4) & 1) * 8;
    const int bK   = ((lane >> 3) & 1) * 8;

    float acc[2][4][4];
#pragma unroll
    for (int i = 0; i < 2; i++)
#pragma unroll
        for (int j = 0; j < 4; j++)
#pragma unroll
            for (int k = 0; k < 4; k++) acc[i][j][k] = 0.0f;

    const int nchunk = K / 32;
    float4 sa[2], sb[2];

    auto prefetch = [&](int c) {
        const int kb = c * 32;
        sa[0] = *reinterpret_cast<const float4*>(&A[(long)(rowA + lr0) * ldA + kb + lc4 * 4]);
        sa[1] = *reinterpret_cast<const float4*>(&A[(long)(rowA + lr1) * ldA + kb + lc4 * 4]);
        sb[0] = *reinterpret_cast<const float4*>(&B[(long)(rowB + lr0) * ldB + kb + lc4 * 4]);
        sb[1] = *reinterpret_cast<const float4*>(&B[(long)(rowB + lr1) * ldB + kb + lc4 * 4]);
    };

    auto cvtstore = [&](int st) {
        char* base = smem + st * STAGEB;
        const uint32_t o0 = (uint32_t)(lr0 * ROWB + lc4 * 8);
        const uint32_t o1 = (uint32_t)(lr1 * ROWB + lc4 * 8);
        cvt_store(base + 0 * TILEB, base + 1 * TILEB, o0, sa[0]);
        cvt_store(base + 0 * TILEB, base + 1 * TILEB, o1, sa[1]);
        cvt_store(base + 2 * TILEB, base + 3 * TILEB, o0, sb[0]);
        cvt_store(base + 2 * TILEB, base + 3 * TILEB, o1, sb[1]);
    };

    prefetch(0);
    cvtstore(0);
    __syncthreads();

    const uint32_t sbase = smem_u32(smem);

    for (int c = 0; c < nchunk; c++) {
        const int st = c & 1;

        if (c + 1 < nchunk) prefetch(c + 1);   // LDG latency hides under MMA

        const uint32_t uA  = sbase + st * STAGEB;
        const uint32_t uAl = uA + TILEB;
        const uint32_t uB  = uA + 2 * TILEB;
        const uint32_t uBl = uA + 3 * TILEB;

#pragma unroll
        for (int ks = 0; ks < 2; ks++) {
            uint32_t ah[2][4], al[2][4], bh[4][2], bl[4][2];
#pragma unroll
            for (int mi = 0; mi < 2; mi++) {
                const uint32_t off = (uint32_t)((wm * 32 + mi * 16 + aRow) * ROWB
                                                + (ks * 16 + aK) * 2);
                ldsm_x4(uA + off, ah[mi]);
                ldsm_x4(uAl + off, al[mi]);
            }
#pragma unroll
            for (int nj = 0; nj < 2; nj++) {
                const uint32_t off = (uint32_t)((wn * 32 + nj * 16 + bRow) * ROWB
                                                + (ks * 16 + bK) * 2);
                uint32_t rh[4], rl[4];
                ldsm_x4(uB + off, rh);
                ldsm_x4(uBl + off, rl);
                bh[nj * 2][0] = rh[0]; bh[nj * 2][1] = rh[1];
                bh[nj * 2 + 1][0] = rh[2]; bh[nj * 2 + 1][1] = rh[3];
                bl[nj * 2][0] = rl[0]; bl[nj * 2][1] = rl[1];
                bl[nj * 2 + 1][0] = rl[2]; bl[nj * 2 + 1][1] = rl[3];
            }
#pragma unroll
            for (int mi = 0; mi < 2; mi++)
#pragma unroll
                for (int ni = 0; ni < 4; ni++) {
                    mma_bf16(acc[mi][ni], ah[mi], bh[ni]);
                    mma_bf16(acc[mi][ni], ah[mi], bl[ni]);
                    mma_bf16(acc[mi][ni], al[mi], bh[ni]);
                }
        }

        if (c + 1 < nchunk) cvtstore(st ^ 1);  // overlaps with tail of MMA stream
        __syncthreads();
    }

    // Epilogue (fp32)
    const int g = lane >> 2, t = lane & 3;
#pragma unroll
    for (int mi = 0; mi < 2; mi++) {
#pragma unroll
        for (int half = 0; half < 2; half++) {
            const long r = (long)(rowA + wm * 32 + mi * 16 + g + half * 8);
#pragma unroll
            for (int ni = 0; ni < 4; ni++) {
                const int col = rowB + wn * 32 + ni * 8 + t * 2;
                *reinterpret_cast<float2*>(&C[r * ldC + col]) =
                    make_float2(acc[mi][ni][half * 2 + 0] * alpha,
                                acc[mi][ni][half * 2 + 1] * alpha);
            }
        }
    }
}

// ---------------------------------------------------------------------------
// Transpose: out[c,r] = in[r,c]; input ld = ldIn, output ld = R; batched via z
// ---------------------------------------------------------------------------
__global__ __launch_bounds__(256)
void transpose_kernel(const float* __restrict__ in, float* __restrict__ out,
                      int R, int ldIn, long sIn, long sOut)
{
    __shared__ float t[32][33];
    in  += (long)blockIdx.z * sIn;
    out += (long)blockIdx.z * sOut;
    const int rb = blockIdx.y * 32, cb = blockIdx.x * 32;
    const int x = threadIdx.x, y = threadIdx.y;  // 32 x 8
#pragma unroll
    for (int j = 0; j < 32; j += 8)
        t[y + j][x] = in[(long)(rb + y + j) * ldIn + cb + x];
    __syncthreads();
#pragma unroll
    for (int j = 0; j < 32; j += 8)
        out[(long)(cb + y + j) * R + rb + x] = t[x][y + j];
}

// ---------------------------------------------------------------------------
// Row softmax over SEQ=2048 columns, in-place fp32. One 256-thread CTA/row.
// ---------------------------------------------------------------------------
__global__ __launch_bounds__(256)
void softmax_kernel(float* __restrict__ S)
{
    float* p = S + (long)blockIdx.x * SEQ;
    const int tid  = threadIdx.x;
    const int lane = tid & 31;
    const int warp = tid >> 5;
    __shared__ float red[8];

    float4 u0 = *reinterpret_cast<const float4*>(&p[tid * 8]);
    float4 u1 = *reinterpret_cast<const float4*>(&p[tid * 8 + 4]);
    float v[8] = {u0.x, u0.y, u0.z, u0.w, u1.x, u1.y, u1.z, u1.w};

    float m = v[0];
#pragma unroll
    for (int i = 1; i < 8; i++) m = fmaxf(m, v[i]);
#pragma unroll
    for (int o = 16; o > 0; o >>= 1) m = fmaxf(m, __shfl_xor_sync(0xffffffffu, m, o));
    if (lane == 0) red[warp] = m;
    __syncthreads();
    m = red[0];
#pragma unroll
    for (int i = 1; i < 8; i++) m = fmaxf(m, red[i]);
    __syncthreads();

    float s = 0.0f;
#pragma unroll
    for (int i = 0; i < 8; i++) { v[i] = __expf(v[i] - m); s += v[i]; }
#pragma unroll
    for (int o = 16; o > 0; o >>= 1) s += __shfl_xor_sync(0xffffffffu, s, o);
    if (lane == 0) red[warp] = s;
    __syncthreads();
    s = red[0];
#pragma unroll
    for (int i = 1; i < 8; i++) s += red[i];

    float inv = __frcp_rn(s);
    float4 w0, w1;
    w0.x = v[0] * inv; w0.y = v[1] * inv; w0.z = v[2] * inv; w0.w = v[3] * inv;
    w1.x = v[4] * inv; w1.y = v[5] * inv; w1.z = v[6] * inv; w1.w = v[7] * inv;
    *reinterpret_cast<float4*>(&p[tid * 8])     = w0;
    *reinterpret_cast<float4*>(&p[tid * 8 + 4]) = w1;
}

// ---------------------------------------------------------------------------
extern "C" void kernel_launch(void* const* d_in, const int* in_sizes, int n_in,
                              void* d_out, int out_size)
{
    const float* x  = (const float*)d_in[0];
    const float* Wq = (const float*)d_in[1];
    const float* Wk = (const float*)d_in[2];
    const float* Wv = (const float*)d_in[3];
    float* out = (float*)d_out;

    float *QKV, *Vt, *S, *WT;
    cudaGetSymbolAddress((void**)&QKV, g_QKV);
    cudaGetSymbolAddress((void**)&Vt,  g_Vt);
    cudaGetSymbolAddress((void**)&S,   g_S);
    cudaGetSymbolAddress((void**)&WT,  g_WT);

    cudaFuncSetAttribute(tc_gemm4, cudaFuncAttributeMaxDynamicSharedMemorySize, SMEMB);

    const dim3 gemmBlk(512);   // tc_gemm4 only
    const dim3 blk256(256);    // softmax
    const dim3 tblk(32, 8);    // transpose
    const int M_proj = BATCH * SEQ;  // 16384

    // 1) Transpose weights into concat WT [1536, 512] (K-major rows)
    {
        dim3 g(DIM / 32, DIM / 32, 1);
        transpose_kernel<<<g, tblk>>>(Wq, WT + 0L * DIM * DIM, DIM, DIM, 0, 0);
        transpose_kernel<<<g, tblk>>>(Wk, WT + 1L * DIM * DIM, DIM, DIM, 0, 0);
        transpose_kernel<<<g, tblk>>>(Wv, WT + 2L * DIM * DIM, DIM, DIM, 0, 0);
    }

    // 2) Fused QKV projection: QKV[16384,1536] = x[16384,512] @ WT^T
    {
        dim3 g(NQKV / 128, M_proj / 128, 1);
        tc_gemm4<<<g, gemmBlk, SMEMB>>>(x, WT, QKV, M_proj, NQKV, DIM,
                                        DIM, DIM, NQKV, 0, 0, 0, 1.0f);
    }

    // 3) Transpose V (QKV cols 1024..1535) per batch -> Vt [512, 2048]
    {
        dim3 g(DIM / 32, SEQ / 32, BATCH);
        transpose_kernel<<<g, tblk>>>(QKV + 2 * DIM, Vt, SEQ, NQKV,
                                      (long)SEQ * NQKV, (long)DIM * SEQ);
    }

    // 4) Scores: S[b] = Q[b] @ K[b]^T / sqrt(D)
    {
        const float scale = 0.044194173824159216f;  // 1/sqrt(512)
        dim3 g(SEQ / 128, SEQ / 128, BATCH);
        tc_gemm4<<<g, gemmBlk, SMEMB>>>(QKV, QKV + DIM, S, SEQ, SEQ, DIM,
                                        NQKV, NQKV, SEQ,
                                        (long)SEQ * NQKV, (long)SEQ * NQKV,
                                        (long)SEQ * SEQ, scale);
    }

    // 5) Softmax rows (in place)
    softmax_kernel<<<BATCH * SEQ, blk256>>>(S);

    // 6) out[b] = P[b] @ Vt[b]^T
    {
        dim3 g(DIM / 128, SEQ / 128, BATCH);
        tc_gemm4<<<g, gemmBlk, SMEMB>>>(S, Vt, out, SEQ, DIM, SEQ,
                                        SEQ, SEQ, DIM,
                                        (long)SEQ * SEQ, (long)DIM * SEQ,
                                        (long)SEQ * DIM, 1.0f);
    }
}

// round 8
// speedup vs baseline: 1.0088x; 1.0088x over previous
#include <cuda_runtime.h>
#include <cuda_bf16.h>
#include <cstdint>

#define BATCH 8
#define SEQ   2048
#define DIM   512
#define NQKV  1536   // 3*DIM

// ---------------------------------------------------------------------------
// Scratch (device globals) — all GEMM operands pre-split into bf16 hi/lo
// ---------------------------------------------------------------------------
__device__ __align__(16) __nv_bfloat16 g_xhi [(long)BATCH * SEQ * DIM];
__device__ __align__(16) __nv_bfloat16 g_xlo [(long)BATCH * SEQ * DIM];
__device__ __align__(16) __nv_bfloat16 g_WThi[(long)NQKV * DIM];
__device__ __align__(16) __nv_bfloat16 g_WTlo[(long)NQKV * DIM];
__device__ __align__(16) __nv_bfloat16 g_QKVhi[(long)BATCH * SEQ * NQKV];
__device__ __align__(16) __nv_bfloat16 g_QKVlo[(long)BATCH * SEQ * NQKV];
__device__ __align__(16) __nv_bfloat16 g_Vthi[(long)BATCH * DIM * SEQ];
__device__ __align__(16) __nv_bfloat16 g_Vtlo[(long)BATCH * DIM * SEQ];
__device__ __align__(16) __nv_bfloat16 g_Phi [(long)BATCH * SEQ * SEQ];
__device__ __align__(16) __nv_bfloat16 g_Plo [(long)BATCH * SEQ * SEQ];
__device__ __align__(16) float         g_S   [(long)BATCH * SEQ * SEQ];

// ---------------------------------------------------------------------------
// PTX helpers (baseline ISA: ldmatrix, mma.sync, cp.async — sm_80+)
// ---------------------------------------------------------------------------
__device__ __forceinline__ uint32_t smem_u32(const void* p) {
    uint32_t a;
    asm("{ .reg .u64 t; cvta.to.shared.u64 t, %1; cvt.u32.u64 %0, t; }"
        : "=r"(a) : "l"(p));
    return a;
}
__device__ __forceinline__ void ldsm_x4(uint32_t addr, uint32_t* r) {
    asm volatile("ldmatrix.sync.aligned.m8n8.x4.shared.b16 {%0,%1,%2,%3}, [%4];"
                 : "=r"(r[0]), "=r"(r[1]), "=r"(r[2]), "=r"(r[3]) : "r"(addr));
}
__device__ __forceinline__ void mma_bf16(float* c, const uint32_t* a, const uint32_t* b) {
    asm volatile(
        "mma.sync.aligned.m16n8k16.row.col.f32.bf16.bf16.f32 "
        "{%0,%1,%2,%3}, {%4,%5,%6,%7}, {%8,%9}, {%0,%1,%2,%3};"
        : "+f"(c[0]), "+f"(c[1]), "+f"(c[2]), "+f"(c[3])
        : "r"(a[0]), "r"(a[1]), "r"(a[2]), "r"(a[3]), "r"(b[0]), "r"(b[1]));
}
__device__ __forceinline__ void cp16(uint32_t dst, const void* src) {
    asm volatile("cp.async.cg.shared.global [%0], [%1], 16;" :: "r"(dst), "l"(src));
}
#define CP_COMMIT() asm volatile("cp.async.commit_group;" ::: "memory")
#define CP_WAIT1()  asm volatile("cp.async.wait_group 1;" ::: "memory")

__device__ __forceinline__ void split_bf16(float v, __nv_bfloat16& h, __nv_bfloat16& l) {
    h = __float2bfloat16_rn(v);
    l = __float2bfloat16_rn(v - __bfloat162float(h));
}

// ---------------------------------------------------------------------------
// Tensor-core GEMM: C[M,N] = alpha * A[M,K] @ B[N,K]^T
// A,B pre-split bf16 hi/lo (K-major). 3 MMA terms: hihi + hilo + lohi.
// CTA tile 256x128, k-chunk 32, 3-stage cp.async pipeline, 1 sync/chunk.
// 512 threads / 16 warps: 4M x 4N grid of 64x32 warp tiles.
// EPI 0: fp32 out; EPI 1: bf16 hi/lo pair out.
// ---------------------------------------------------------------------------
#define ROWB    80                    // padded row (40 bf16): conflict-free ldsm
#define A_TILEB (256 * ROWB)          // 20480
#define B_TILEB (128 * ROWB)          // 10240
#define STAGEB  (2 * A_TILEB + 2 * B_TILEB)  // 61440: Ahi, Alo, Bhi, Blo
#define NSTAGE  3
#define SMEMB   (NSTAGE * STAGEB)     // 184320

template <int EPI>
__global__ __launch_bounds__(512, 1)
void tc_gemm5(const __nv_bfloat16* __restrict__ Ahi, const __nv_bfloat16* __restrict__ Alo,
              const __nv_bfloat16* __restrict__ Bhi, const __nv_bfloat16* __restrict__ Blo,
              float* __restrict__ Cf,
              __nv_bfloat16* __restrict__ Chi, __nv_bfloat16* __restrict__ Clo,
              int M, int N, int K, int ldA, int ldB, int ldC,
              long sA, long sB, long sC, float alpha)
{
    extern __shared__ __align__(16) char smem[];
    const uint32_t sbase = smem_u32(smem);

    const long zb = blockIdx.z;
    Ahi += zb * sA; Alo += zb * sA;
    Bhi += zb * sB; Blo += zb * sB;

    const int tid  = threadIdx.x;
    const int wid  = tid >> 5;
    const int lane = tid & 31;
    const int wm   = wid & 3;   // 4 warps along M: 64 rows each
    const int wn   = wid >> 2;  // 4 warps along N: 32 cols each

    const int rowA = blockIdx.y * 256;
    const int rowB = blockIdx.x * 128;

    // ldmatrix lane selectors
    const int aRow = lane & 15;
    const int aK   = (lane >> 4) * 8;
    const int bRow = (lane & 7) + ((lane >> 4) & 1) * 8;
    const int bK   = ((lane >> 3) & 1) * 8;

    // cp.async loader mapping: A has 1024 16B-chunks/tile (2 per thread),
    // B has 512 (1 per thread). chunk -> row = c>>2, col16 = c&3.
    const int ar0 = tid >> 2,        ac0 = tid & 3;          // A chunk tid
    const int ar1 = (tid + 512) >> 2, ac1 = (tid + 512) & 3; // A chunk tid+512
    const int br  = tid >> 2,        bc  = tid & 3;          // B chunk tid

    float acc[4][4][4];
#pragma unroll
    for (int i = 0; i < 4; i++)
#pragma unroll
        for (int j = 0; j < 4; j++)
#pragma unroll
            for (int k = 0; k < 4; k++) acc[i][j][k] = 0.0f;

    const int nchunk = K / 32;

    auto load_stage = [&](int slot, int c) {
        const int kb = c * 32;
        const uint32_t sb = sbase + slot * STAGEB;
        {   // A hi/lo: 2 chunks each
            const uint32_t s0 = (uint32_t)(ar0 * ROWB + ac0 * 16);
            const uint32_t s1 = (uint32_t)(ar1 * ROWB + ac1 * 16);
            const long g0 = (long)(rowA + ar0) * ldA + kb + ac0 * 8;
            const long g1 = (long)(rowA + ar1) * ldA + kb + ac1 * 8;
            cp16(sb + s0, Ahi + g0);
            cp16(sb + s1, Ahi + g1);
            cp16(sb + A_TILEB + s0, Alo + g0);
            cp16(sb + A_TILEB + s1, Alo + g1);
        }
        {   // B hi/lo: 1 chunk each
            const uint32_t s0 = (uint32_t)(br * ROWB + bc * 16);
            const long g0 = (long)(rowB + br) * ldB + kb + bc * 8;
            cp16(sb + 2 * A_TILEB + s0, Bhi + g0);
            cp16(sb + 2 * A_TILEB + B_TILEB + s0, Blo + g0);
        }
    };

    auto compute = [&](int slot) {
        const uint32_t uAh = sbase + slot * STAGEB;
        const uint32_t uAl = uAh + A_TILEB;
        const uint32_t uBh = uAh + 2 * A_TILEB;
        const uint32_t uBl = uBh + B_TILEB;
#pragma unroll
        for (int ks = 0; ks < 2; ks++) {
            uint32_t bh[4][2], bl[4][2];
#pragma unroll
            for (int nj = 0; nj < 2; nj++) {
                const uint32_t off = (uint32_t)((wn * 32 + nj * 16 + bRow) * ROWB
                                                + (ks * 16 + bK) * 2);
                uint32_t rh[4], rl[4];
                ldsm_x4(uBh + off, rh);
                ldsm_x4(uBl + off, rl);
                bh[nj * 2][0] = rh[0]; bh[nj * 2][1] = rh[1];
                bh[nj * 2 + 1][0] = rh[2]; bh[nj * 2 + 1][1] = rh[3];
                bl[nj * 2][0] = rl[0]; bl[nj * 2][1] = rl[1];
                bl[nj * 2 + 1][0] = rl[2]; bl[nj * 2 + 1][1] = rl[3];
            }
#pragma unroll
            for (int mi = 0; mi < 4; mi++) {
                uint32_t ah[4], al[4];
                const uint32_t off = (uint32_t)((wm * 64 + mi * 16 + aRow) * ROWB
                                                + (ks * 16 + aK) * 2);
                ldsm_x4(uAh + off, ah);
                ldsm_x4(uAl + off, al);
#pragma unroll
                for (int ni = 0; ni < 4; ni++) {
                    mma_bf16(acc[mi][ni], ah, bh[ni]);
                    mma_bf16(acc[mi][ni], ah, bl[ni]);
                    mma_bf16(acc[mi][ni], al, bh[ni]);
                }
            }
        }
    };

    // 3-stage pipeline
    load_stage(0, 0); CP_COMMIT();
    load_stage(1, 1); CP_COMMIT();

    for (int c = 0; c < nchunk; c++) {
        CP_WAIT1();          // stage c complete (<=1 group outstanding)
        __syncthreads();     // all warps past compute(c-1); stage c visible
        compute(c % NSTAGE);
        if (c + 2 < nchunk) load_stage((c + 2) % NSTAGE, c + 2);
        CP_COMMIT();         // uniform group counting
    }

    // Epilogue
    const int g = lane >> 2, t = lane & 3;
#pragma unroll
    for (int mi = 0; mi < 4; mi++) {
#pragma unroll
        for (int half = 0; half < 2; half++) {
            const long r = (long)(rowA + wm * 64 + mi * 16 + g + half * 8);
#pragma unroll
            for (int ni = 0; ni < 4; ni++) {
                const int col = rowB + wn * 32 + ni * 8 + t * 2;
                float v0 = acc[mi][ni][half * 2 + 0] * alpha;
                float v1 = acc[mi][ni][half * 2 + 1] * alpha;
                if (EPI == 0) {
                    *reinterpret_cast<float2*>(&Cf[zb * sC + r * ldC + col]) =
                        make_float2(v0, v1);
                } else {
                    __nv_bfloat16 h0, l0, h1, l1;
                    split_bf16(v0, h0, l0);
                    split_bf16(v1, h1, l1);
                    __nv_bfloat162 hp, lp;
                    hp.x = h0; hp.y = h1; lp.x = l0; lp.y = l1;
                    *reinterpret_cast<__nv_bfloat162*>(&Chi[zb * sC + r * ldC + col]) = hp;
                    *reinterpret_cast<__nv_bfloat162*>(&Clo[zb * sC + r * ldC + col]) = lp;
                }
            }
        }
    }
}

// ---------------------------------------------------------------------------
// Elementwise fp32 -> bf16 hi/lo split (x)
// ---------------------------------------------------------------------------
__global__ __launch_bounds__(256)
void cvt_pair_kernel(const float* __restrict__ in, __nv_bfloat16* __restrict__ hi,
                     __nv_bfloat16* __restrict__ lo, long n)
{
    long i = ((long)blockIdx.x * 256 + threadIdx.x) * 4;
    if (i >= n) return;
    float4 v = *reinterpret_cast<const float4*>(in + i);
    __nv_bfloat16 h[4], l[4];
    split_bf16(v.x, h[0], l[0]);
    split_bf16(v.y, h[1], l[1]);
    split_bf16(v.z, h[2], l[2]);
    split_bf16(v.w, h[3], l[3]);
    *reinterpret_cast<uint2*>(hi + i) = *reinterpret_cast<uint2*>(h);
    *reinterpret_cast<uint2*>(lo + i) = *reinterpret_cast<uint2*>(l);
}

// ---------------------------------------------------------------------------
// Transpose fp32 [R,C] -> bf16 hi/lo [C,R] with output row offset (weights)
// ---------------------------------------------------------------------------
__global__ __launch_bounds__(256)
void transpose_cvt_w(const float* __restrict__ in, __nv_bfloat16* __restrict__ hi,
                     __nv_bfloat16* __restrict__ lo, int R, int C, int roff)
{
    __shared__ float t[32][33];
    const int rb = blockIdx.y * 32, cb = blockIdx.x * 32;
    const int x = threadIdx.x, y = threadIdx.y;
#pragma unroll
    for (int j = 0; j < 32; j += 8)
        t[y + j][x] = in[(long)(rb + y + j) * C + cb + x];
    __syncthreads();
#pragma unroll
    for (int j = 0; j < 32; j += 8) {
        float v = t[x][y + j];
        __nv_bfloat16 h, l;
        split_bf16(v, h, l);
        const long o = (long)(roff + cb + y + j) * R + rb + x;
        hi[o] = h;
        lo[o] = l;
    }
}

// ---------------------------------------------------------------------------
// Transpose bf16 pair: in [R,C] (ld ldIn) -> out [C,R] (ld R), batched via z
// ---------------------------------------------------------------------------
__global__ __launch_bounds__(256)
void transpose_pair_kernel(const __nv_bfloat16* __restrict__ ihi,
                           const __nv_bfloat16* __restrict__ ilo,
                           __nv_bfloat16* __restrict__ ohi,
                           __nv_bfloat16* __restrict__ olo,
                           int R, int ldIn, long sIn, long sOut)
{
    __shared__ __nv_bfloat16 th[32][34];
    __shared__ __nv_bfloat16 tl[32][34];
    ihi += (long)blockIdx.z * sIn;  ilo += (long)blockIdx.z * sIn;
    ohi += (long)blockIdx.z * sOut; olo += (long)blockIdx.z * sOut;
    const int rb = blockIdx.y * 32, cb = blockIdx.x * 32;
    const int x = threadIdx.x, y = threadIdx.y;
#pragma unroll
    for (int j = 0; j < 32; j += 8) {
        th[y + j][x] = ihi[(long)(rb + y + j) * ldIn + cb + x];
        tl[y + j][x] = ilo[(long)(rb + y + j) * ldIn + cb + x];
    }
    __syncthreads();
#pragma unroll
    for (int j = 0; j < 32; j += 8) {
        ohi[(long)(cb + y + j) * R + rb + x] = th[x][y + j];
        olo[(long)(cb + y + j) * R + rb + x] = tl[x][y + j];
    }
}

// ---------------------------------------------------------------------------
// Row softmax over SEQ cols, fp32 in -> bf16 hi/lo probs out. 256 thr/row.
// ---------------------------------------------------------------------------
__global__ __launch_bounds__(256)
void softmax_pair_kernel(const float* __restrict__ S, __nv_bfloat16* __restrict__ Phi,
                         __nv_bfloat16* __restrict__ Plo)
{
    const float* p = S + (long)blockIdx.x * SEQ;
    __nv_bfloat16* ph = Phi + (long)blockIdx.x * SEQ;
    __nv_bfloat16* pl = Plo + (long)blockIdx.x * SEQ;
    const int tid  = threadIdx.x;
    const int lane = tid & 31;
    const int warp = tid >> 5;
    __shared__ float red[8];

    float4 u0 = *reinterpret_cast<const float4*>(&p[tid * 8]);
    float4 u1 = *reinterpret_cast<const float4*>(&p[tid * 8 + 4]);
    float v[8] = {u0.x, u0.y, u0.z, u0.w, u1.x, u1.y, u1.z, u1.w};

    float m = v[0];
#pragma unroll
    for (int i = 1; i < 8; i++) m = fmaxf(m, v[i]);
#pragma unroll
    for (int o = 16; o > 0; o >>= 1) m = fmaxf(m, __shfl_xor_sync(0xffffffffu, m, o));
    if (lane == 0) red[warp] = m;
    __syncthreads();
    m = red[0];
#pragma unroll
    for (int i = 1; i < 8; i++) m = fmaxf(m, red[i]);
    __syncthreads();

    float s = 0.0f;
#pragma unroll
    for (int i = 0; i < 8; i++) { v[i] = __expf(v[i] - m); s += v[i]; }
#pragma unroll
    for (int o = 16; o > 0; o >>= 1) s += __shfl_xor_sync(0xffffffffu, s, o);
    if (lane == 0) red[warp] = s;
    __syncthreads();
    s = red[0];
#pragma unroll
    for (int i = 1; i < 8; i++) s += red[i];

    const float inv = __frcp_rn(s);
    __nv_bfloat16 h[8], l[8];
#pragma unroll
    for (int i = 0; i < 8; i++) split_bf16(v[i] * inv, h[i], l[i]);
    *reinterpret_cast<uint4*>(&ph[tid * 8]) = *reinterpret_cast<uint4*>(h);
    *reinterpret_cast<uint4*>(&pl[tid * 8]) = *reinterpret_cast<uint4*>(l);
}

// ---------------------------------------------------------------------------
extern "C" void kernel_launch(void* const* d_in, const int* in_sizes, int n_in,
                              void* d_out, int out_size)
{
    const float* x  = (const float*)d_in[0];
    const float* Wq = (const float*)d_in[1];
    const float* Wk = (const float*)d_in[2];
    const float* Wv = (const float*)d_in[3];
    float* out = (float*)d_out;

    __nv_bfloat16 *xhi, *xlo, *WThi, *WTlo, *QKVhi, *QKVlo, *Vthi, *Vtlo, *Phi, *Plo;
    float* S;
    cudaGetSymbolAddress((void**)&xhi,   g_xhi);
    cudaGetSymbolAddress((void**)&xlo,   g_xlo);
    cudaGetSymbolAddress((void**)&WThi,  g_WThi);
    cudaGetSymbolAddress((void**)&WTlo,  g_WTlo);
    cudaGetSymbolAddress((void**)&QKVhi, g_QKVhi);
    cudaGetSymbolAddress((void**)&QKVlo, g_QKVlo);
    cudaGetSymbolAddress((void**)&Vthi,  g_Vthi);
    cudaGetSymbolAddress((void**)&Vtlo,  g_Vtlo);
    cudaGetSymbolAddress((void**)&Phi,   g_Phi);
    cudaGetSymbolAddress((void**)&Plo,   g_Plo);
    cudaGetSymbolAddress((void**)&S,     g_S);

    cudaFuncSetAttribute(tc_gemm5<0>, cudaFuncAttributeMaxDynamicSharedMemorySize, SMEMB);
    cudaFuncSetAttribute(tc_gemm5<1>, cudaFuncAttributeMaxDynamicSharedMemorySize, SMEMB);

    const dim3 gemmBlk(512);
    const dim3 blk256(256);
    const dim3 tblk(32, 8);
    const int M_proj = BATCH * SEQ;      // 16384
    const long nx = (long)M_proj * DIM;

    // 1) Split x -> bf16 hi/lo
    cvt_pair_kernel<<<(unsigned)((nx / 4 + 255) / 256), blk256>>>(x, xhi, xlo, nx);

    // 2) Transpose+split weights -> WT [1536, 512] K-major pair
    {
        dim3 g(DIM / 32, DIM / 32);
        transpose_cvt_w<<<g, tblk>>>(Wq, WThi, WTlo, DIM, DIM, 0);
        transpose_cvt_w<<<g, tblk>>>(Wk, WThi, WTlo, DIM, DIM, DIM);
        transpose_cvt_w<<<g, tblk>>>(Wv, WThi, WTlo, DIM, DIM, 2 * DIM);
    }

    // 3) Fused QKV projection: QKV[16384,1536] = x @ WT^T (pair out)
    {
        dim3 g(NQKV / 128, M_proj / 256, 1);
        tc_gemm5<1><<<g, gemmBlk, SMEMB>>>(xhi, xlo, WThi, WTlo,
                                           nullptr, QKVhi, QKVlo,
                                           M_proj, NQKV, DIM, DIM, DIM, NQKV,
                                           0, 0, 0, 1.0f);
    }

    // 4) Transpose V (QKV cols 1024..1535) -> Vt [512, 2048] pair, per batch
    {
        dim3 g(DIM / 32, SEQ / 32, BATCH);
        transpose_pair_kernel<<<g, tblk>>>(QKVhi + 2 * DIM, QKVlo + 2 * DIM,
                                           Vthi, Vtlo, SEQ, NQKV,
                                           (long)SEQ * NQKV, (long)DIM * SEQ);
    }

    // 5) Scores: S[b] = Q[b] @ K[b]^T / sqrt(D)  (fp32 out)
    {
        const float scale = 0.044194173824159216f;  // 1/sqrt(512)
        dim3 g(SEQ / 128, SEQ / 256, BATCH);
        tc_gemm5<0><<<g, gemmBlk, SMEMB>>>(QKVhi, QKVlo, QKVhi + DIM, QKVlo + DIM,
                                           S, nullptr, nullptr,
                                           SEQ, SEQ, DIM, NQKV, NQKV, SEQ,
                                           (long)SEQ * NQKV, (long)SEQ * NQKV,
                                           (long)SEQ * SEQ, scale);
    }

    // 6) Softmax -> P pair
    softmax_pair_kernel<<<BATCH * SEQ, blk256>>>(S, Phi, Plo);

    // 7) out[b] = P[b] @ Vt[b]^T  (fp32 out)
    {
        dim3 g(DIM / 128, SEQ / 256, BATCH);
        tc_gemm5<0><<<g, gemmBlk, SMEMB>>>(Phi, Plo, Vthi, Vtlo,
                                           out, nullptr, nullptr,
                                           SEQ, DIM, SEQ, SEQ, SEQ, DIM,
                                           (long)SEQ * SEQ, (long)DIM * SEQ,
                                           (long)SEQ * DIM, 1.0f);
    }
}

// round 9
// speedup vs baseline: 1.0614x; 1.0522x over previous
#include <cuda_runtime.h>
#include <cuda_bf16.h>
#include <cstdint>

#define BATCH 8
#define SEQ   2048
#define DIM   512
#define NQKV  1536   // 3*DIM

// ---------------------------------------------------------------------------
// Scratch (device globals)
// ---------------------------------------------------------------------------
__device__ __align__(16) float g_QKV[(long)BATCH * SEQ * NQKV];  // 96 MB
__device__ __align__(16) float g_Vt [(long)BATCH * DIM * SEQ];   // 32 MB
__device__ __align__(16) float g_S  [(long)BATCH * SEQ * SEQ];   // 128 MB
__device__ __align__(16) float g_WT [(long)NQKV * DIM];          // 3 MB

// ---------------------------------------------------------------------------
// PTX helpers (baseline ISA: ldmatrix + mma.sync, sm_80+)
// ---------------------------------------------------------------------------
__device__ __forceinline__ uint32_t smem_u32(const void* p) {
    uint32_t a;
    asm("{ .reg .u64 t; cvta.to.shared.u64 t, %1; cvt.u32.u64 %0, t; }"
        : "=r"(a) : "l"(p));
    return a;
}
__device__ __forceinline__ void ldsm_x4(uint32_t addr, uint32_t* r) {
    asm volatile("ldmatrix.sync.aligned.m8n8.x4.shared.b16 {%0,%1,%2,%3}, [%4];"
                 : "=r"(r[0]), "=r"(r[1]), "=r"(r[2]), "=r"(r[3]) : "r"(addr));
}
__device__ __forceinline__ void mma_bf16(float* c, const uint32_t* a, const uint32_t* b) {
    asm volatile(
        "mma.sync.aligned.m16n8k16.row.col.f32.bf16.bf16.f32 "
        "{%0,%1,%2,%3}, {%4,%5,%6,%7}, {%8,%9}, {%0,%1,%2,%3};"
        : "+f"(c[0]), "+f"(c[1]), "+f"(c[2]), "+f"(c[3])
        : "r"(a[0]), "r"(a[1]), "r"(a[2]), "r"(a[3]), "r"(b[0]), "r"(b[1]));
}

// Convert float4 -> hi/lo bf16 pairs and store 8B each to smem
__device__ __forceinline__ void cvt_store(char* hi, char* lo, uint32_t off, float4 v) {
    __nv_bfloat162 h01 = __floats2bfloat162_rn(v.x, v.y);
    __nv_bfloat162 h23 = __floats2bfloat162_rn(v.z, v.w);
    __nv_bfloat162 l01 = __floats2bfloat162_rn(v.x - __bfloat162float(h01.x),
                                               v.y - __bfloat162float(h01.y));
    __nv_bfloat162 l23 = __floats2bfloat162_rn(v.z - __bfloat162float(h23.x),
                                               v.w - __bfloat162float(h23.y));
    *reinterpret_cast<uint2*>(hi + off) =
        make_uint2(*reinterpret_cast<uint32_t*>(&h01), *reinterpret_cast<uint32_t*>(&h23));
    *reinterpret_cast<uint2*>(lo + off) =
        make_uint2(*reinterpret_cast<uint32_t*>(&l01), *reinterpret_cast<uint32_t*>(&l23));
}

// ---------------------------------------------------------------------------
// Tensor-core GEMM: C[M,N] = alpha * A[M,K] @ B[N,K]^T  (fp32 in/out)
// In-kernel split precision (hi+lo bf16, 3 MMA terms), CTA tile 128x128,
// K-CHUNK 64 (8 chunk boundaries on K=512 instead of 16), double-buffered
// smem, 1 sync per chunk. 512 threads / 16 warps, 32x32 warp tiles.
// ---------------------------------------------------------------------------
#define KC     64
#define ROWB   144                 // 64 bf16 = 128B + 16B pad: conflict-free ldsm
#define TILEB  (128 * ROWB)        // 18432
#define STAGEB (4 * TILEB)         // Ahi, Alo, Bhi, Blo = 73728
#define SMEMB  (2 * STAGEB)        // 147456

__global__ __launch_bounds__(512, 1)
void tc_gemm6(const float* __restrict__ A, const float* __restrict__ B,
              float* __restrict__ C, int M, int N, int K,
              int ldA, int ldB, int ldC, long sA, long sB, long sC, float alpha)
{
    extern __shared__ __align__(16) char smem[];

    const long zb = blockIdx.z;
    A += zb * sA;
    B += zb * sB;
    C += zb * sC;

    const int tid  = threadIdx.x;
    const int wid  = tid >> 5;
    const int lane = tid & 31;
    const int wm   = wid & 3;   // 4 warps along M (32 rows each)
    const int wn   = wid >> 2;  // 4 warps along N (32 cols each)

    const int rowA = blockIdx.y * 128;
    const int rowB = blockIdx.x * 128;

    // Loader mapping: 64-float rows; 16 threads per row; 4 row-iterations
    const int lrow = tid >> 4;        // 0..31, advance by 32 per i
    const int lc4  = tid & 15;        // float4 index within row

    // ldmatrix lane selectors
    const int aRow = lane & 15;
    const int aK   = (lane >> 4) * 8;
    const int bRow = (lane & 7) + ((lane >> 4) & 1) * 8;
    const int bK   = ((lane >> 3) & 1) * 8;

    float acc[2][4][4];
#pragma unroll
    for (int i = 0; i < 2; i++)
#pragma unroll
        for (int j = 0; j < 4; j++)
#pragma unroll
            for (int k = 0; k < 4; k++) acc[i][j][k] = 0.0f;

    const int nchunk = K / KC;
    float4 sa[4], sb[4];

    auto prefetch = [&](int c) {
        const int kb = c * KC;
#pragma unroll
        for (int i = 0; i < 4; i++) {
            const int r = lrow + i * 32;
            sa[i] = *reinterpret_cast<const float4*>(&A[(long)(rowA + r) * ldA + kb + lc4 * 4]);
            sb[i] = *reinterpret_cast<const float4*>(&B[(long)(rowB + r) * ldB + kb + lc4 * 4]);
        }
    };

    auto cvtstore = [&](int st) {
        char* base = smem + st * STAGEB;
#pragma unroll
        for (int i = 0; i < 4; i++) {
            const int r = lrow + i * 32;
            const uint32_t off = (uint32_t)(r * ROWB + lc4 * 8);
            cvt_store(base + 0 * TILEB, base + 1 * TILEB, off, sa[i]);
            cvt_store(base + 2 * TILEB, base + 3 * TILEB, off, sb[i]);
        }
    };

    prefetch(0);
    cvtstore(0);
    __syncthreads();

    const uint32_t sbase = smem_u32(smem);

    for (int c = 0; c < nchunk; c++) {
        const int st = c & 1;

        if (c + 1 < nchunk) prefetch(c + 1);   // LDG latency hides under MMA

        const uint32_t uA  = sbase + st * STAGEB;
        const uint32_t uAl = uA + TILEB;
        const uint32_t uB  = uA + 2 * TILEB;
        const uint32_t uBl = uA + 3 * TILEB;

#pragma unroll
        for (int ks = 0; ks < 4; ks++) {            // 4 k16 steps per 64-chunk
            uint32_t ah[2][4], al[2][4], bh[4][2], bl[4][2];
#pragma unroll
            for (int mi = 0; mi < 2; mi++) {
                const uint32_t off = (uint32_t)((wm * 32 + mi * 16 + aRow) * ROWB
                                                + (ks * 16 + aK) * 2);
                ldsm_x4(uA + off, ah[mi]);
                ldsm_x4(uAl + off, al[mi]);
            }
#pragma unroll
            for (int nj = 0; nj < 2; nj++) {
                const uint32_t off = (uint32_t)((wn * 32 + nj * 16 + bRow) * ROWB
                                                + (ks * 16 + bK) * 2);
                uint32_t rh[4], rl[4];
                ldsm_x4(uB + off, rh);
                ldsm_x4(uBl + off, rl);
                bh[nj * 2][0] = rh[0]; bh[nj * 2][1] = rh[1];
                bh[nj * 2 + 1][0] = rh[2]; bh[nj * 2 + 1][1] = rh[3];
                bl[nj * 2][0] = rl[0]; bl[nj * 2][1] = rl[1];
                bl[nj * 2 + 1][0] = rl[2]; bl[nj * 2 + 1][1] = rl[3];
            }
#pragma unroll
            for (int mi = 0; mi < 2; mi++)
#pragma unroll
                for (int ni = 0; ni < 4; ni++) {
                    mma_bf16(acc[mi][ni], ah[mi], bh[ni]);
                    mma_bf16(acc[mi][ni], ah[mi], bl[ni]);
                    mma_bf16(acc[mi][ni], al[mi], bh[ni]);
                }
        }

        if (c + 1 < nchunk) cvtstore(st ^ 1);  // overlaps with tail of MMA stream
        __syncthreads();
    }

    // Epilogue (fp32)
    const int g = lane >> 2, t = lane & 3;
#pragma unroll
    for (int mi = 0; mi < 2; mi++) {
#pragma unroll
        for (int half = 0; half < 2; half++) {
            const long r = (long)(rowA + wm * 32 + mi * 16 + g + half * 8);
#pragma unroll
            for (int ni = 0; ni < 4; ni++) {
                const int col = rowB + wn * 32 + ni * 8 + t * 2;
                *reinterpret_cast<float2*>(&C[r * ldC + col]) =
                    make_float2(acc[mi][ni][half * 2 + 0] * alpha,
                                acc[mi][ni][half * 2 + 1] * alpha);
            }
        }
    }
}

// ---------------------------------------------------------------------------
// Transpose: out[c,r] = in[r,c]; input ld = ldIn, output ld = R; batched via z
// ---------------------------------------------------------------------------
__global__ __launch_bounds__(256)
void transpose_kernel(const float* __restrict__ in, float* __restrict__ out,
                      int R, int ldIn, long sIn, long sOut)
{
    __shared__ float t[32][33];
    in  += (long)blockIdx.z * sIn;
    out += (long)blockIdx.z * sOut;
    const int rb = blockIdx.y * 32, cb = blockIdx.x * 32;
    const int x = threadIdx.x, y = threadIdx.y;  // 32 x 8
#pragma unroll
    for (int j = 0; j < 32; j += 8)
        t[y + j][x] = in[(long)(rb + y + j) * ldIn + cb + x];
    __syncthreads();
#pragma unroll
    for (int j = 0; j < 32; j += 8)
        out[(long)(cb + y + j) * R + rb + x] = t[x][y + j];
}

// ---------------------------------------------------------------------------
// Row softmax over SEQ=2048 columns, in-place fp32. One 256-thread CTA/row.
// ---------------------------------------------------------------------------
__global__ __launch_bounds__(256)
void softmax_kernel(float* __restrict__ S)
{
    float* p = S + (long)blockIdx.x * SEQ;
    const int tid  = threadIdx.x;
    const int lane = tid & 31;
    const int warp = tid >> 5;
    __shared__ float red[8];

    float4 u0 = *reinterpret_cast<const float4*>(&p[tid * 8]);
    float4 u1 = *reinterpret_cast<const float4*>(&p[tid * 8 + 4]);
    float v[8] = {u0.x, u0.y, u0.z, u0.w, u1.x, u1.y, u1.z, u1.w};

    float m = v[0];
#pragma unroll
    for (int i = 1; i < 8; i++) m = fmaxf(m, v[i]);
#pragma unroll
    for (int o = 16; o > 0; o >>= 1) m = fmaxf(m, __shfl_xor_sync(0xffffffffu, m, o));
    if (lane == 0) red[warp] = m;
    __syncthreads();
    m = red[0];
#pragma unroll
    for (int i = 1; i < 8; i++) m = fmaxf(m, red[i]);
    __syncthreads();

    float s = 0.0f;
#pragma unroll
    for (int i = 0; i < 8; i++) { v[i] = __expf(v[i] - m); s += v[i]; }
#pragma unroll
    for (int o = 16; o > 0; o >>= 1) s += __shfl_xor_sync(0xffffffffu, s, o);
    if (lane == 0) red[warp] = s;
    __syncthreads();
    s = red[0];
#pragma unroll
    for (int i = 1; i < 8; i++) s += red[i];

    float inv = __frcp_rn(s);
    float4 w0, w1;
    w0.x = v[0] * inv; w0.y = v[1] * inv; w0.z = v[2] * inv; w0.w = v[3] * inv;
    w1.x = v[4] * inv; w1.y = v[5] * inv; w1.z = v[6] * inv; w1.w = v[7] * inv;
    *reinterpret_cast<float4*>(&p[tid * 8])     = w0;
    *reinterpret_cast<float4*>(&p[tid * 8 + 4]) = w1;
}

// ---------------------------------------------------------------------------
extern "C" void kernel_launch(void* const* d_in, const int* in_sizes, int n_in,
                              void* d_out, int out_size)
{
    const float* x  = (const float*)d_in[0];
    const float* Wq = (const float*)d_in[1];
    const float* Wk = (const float*)d_in[2];
    const float* Wv = (const float*)d_in[3];
    float* out = (float*)d_out;

    float *QKV, *Vt, *S, *WT;
    cudaGetSymbolAddress((void**)&QKV, g_QKV);
    cudaGetSymbolAddress((void**)&Vt,  g_Vt);
    cudaGetSymbolAddress((void**)&S,   g_S);
    cudaGetSymbolAddress((void**)&WT,  g_WT);

    cudaFuncSetAttribute(tc_gemm6, cudaFuncAttributeMaxDynamicSharedMemorySize, SMEMB);

    const dim3 gemmBlk(512);   // tc_gemm6 only
    const dim3 blk256(256);    // softmax
    const dim3 tblk(32, 8);    // transpose
    const int M_proj = BATCH * SEQ;  // 16384

    // 1) Transpose weights into concat WT [1536, 512] (K-major rows)
    {
        dim3 g(DIM / 32, DIM / 32, 1);
        transpose_kernel<<<g, tblk>>>(Wq, WT + 0L * DIM * DIM, DIM, DIM, 0, 0);
        transpose_kernel<<<g, tblk>>>(Wk, WT + 1L * DIM * DIM, DIM, DIM, 0, 0);
        transpose_kernel<<<g, tblk>>>(Wv, WT + 2L * DIM * DIM, DIM, DIM, 0, 0);
    }

    // 2) Fused QKV projection: QKV[16384,1536] = x[16384,512] @ WT^T
    {
        dim3 g(NQKV / 128, M_proj / 128, 1);
        tc_gemm6<<<g, gemmBlk, SMEMB>>>(x, WT, QKV, M_proj, NQKV, DIM,
                                        DIM, DIM, NQKV, 0, 0, 0, 1.0f);
    }

    // 3) Transpose V (QKV cols 1024..1535) per batch -> Vt [512, 2048]
    {
        dim3 g(DIM / 32, SEQ / 32, BATCH);
        transpose_kernel<<<g, tblk>>>(QKV + 2 * DIM, Vt, SEQ, NQKV,
                                      (long)SEQ * NQKV, (long)DIM * SEQ);
    }

    // 4) Scores: S[b] = Q[b] @ K[b]^T / sqrt(D)
    {
        const float scale = 0.044194173824159216f;  // 1/sqrt(512)
        dim3 g(SEQ / 128, SEQ / 128, BATCH);
        tc_gemm6<<<g, gemmBlk, SMEMB>>>(QKV, QKV + DIM, S, SEQ, SEQ, DIM,
                                        NQKV, NQKV, SEQ,
                                        (long)SEQ * NQKV, (long)SEQ * NQKV,
                                        (long)SEQ * SEQ, scale);
    }

    // 5) Softmax rows (in place)
    softmax_kernel<<<BATCH * SEQ, blk256>>>(S);

    // 6) out[b] = P[b] @ Vt[b]^T
    {
        dim3 g(DIM / 128, SEQ / 128, BATCH);
        tc_gemm6<<<g, gemmBlk, SMEMB>>>(S, Vt, out, SEQ, DIM, SEQ,
                                        SEQ, SEQ, DIM,
                                        (long)SEQ * SEQ, (long)DIM * SEQ,
                                        (long)SEQ * DIM, 1.0f);
    }
}